// round 13
// baseline (speedup 1.0000x reference)
#include <cuda_runtime.h>
#include <math.h>

#define NCTA 128
#define NTHR 512
#define WG_F4 12336
#define SMEM_F4 (WG_F4 + 2048)
#define SMEM_BYTES (SMEM_F4 * 16)   // 230144

typedef unsigned long long u64;
typedef ulonglong2 ull2;

__device__ __forceinline__ u64 fma2(u64 a, u64 b, u64 c) {
    u64 d;
    asm("fma.rn.f32x2 %0, %1, %2, %3;" : "=l"(d) : "l"(a), "l"(b), "l"(c));
    return d;
}
__device__ __forceinline__ float hsum(u64 v) {
    union { u64 u; float f[2]; } x; x.u = v;
    return x.f[0] + x.f[1];
}
__device__ __forceinline__ float sigm(float x) { return 1.f / (1.f + expf(-x)); }
__device__ __forceinline__ float softplusf(float x) {
    return fmaxf(x, 0.f) + log1pf(expf(-fabsf(x)));
}
__device__ __forceinline__ void barg(int id) {
    asm volatile("bar.sync %0, 256;" :: "r"(id) : "memory");
}

// ---------------- persistent state ----------------
__device__ float g_emb[64 * 1024];
__device__ float g_det[2][64 * 1024];
__device__ float g_h1[64 * 512];
__device__ float g_hq[64 * 512];
__device__ float g_stoch[64 * 32];
__device__ float g_obsq[64 * 256 * 512];     // obs @ Wq1[:,1024:]^T + bq1
__device__ float g_actemb[64 * 256 * 1024];  // act @ Wsa[:,32:]^T + bsa
__device__ unsigned g_leaf[8][32];
__device__ unsigned g_root;
__device__ volatile unsigned g_gen;

__device__ __forceinline__ void gbar() {
    __syncthreads();
    if (threadIdx.x == 0) {
        __threadfence();
        unsigned gen = g_gen;
        int l = blockIdx.x & 7;
        if (atomicAdd(&g_leaf[l][0], 1u) == 15) {
            g_leaf[l][0] = 0;
            __threadfence();
            if (atomicAdd(&g_root, 1u) == 7) {
                g_root = 0;
                __threadfence();
                g_gen = gen + 1;
            }
        }
        while (g_gen == gen) { }
        __threadfence();
    }
    __syncthreads();
}

// ======== pre-pass A: g_obsq ========
__global__ void __launch_bounds__(256)
obsq_kernel(const float* __restrict__ obs, const float* __restrict__ Wq1,
            const float* __restrict__ bq1) {
    extern __shared__ float4 S[];
    const int tid = threadIdx.x, lane = tid & 31, wrp = tid >> 5;
    const int rt = blockIdx.x >> 2, ct = blockIdx.x & 3;
    const int r0 = rt * 64, c0 = ct * 128;
    const int rh = wrp >> 2, cgq = wrp & 3;

    u64 acc[32];
    #pragma unroll
    for (int j = 0; j < 32; ++j) acc[j] = 0ull;

    for (int c = 0; c < 16; ++c) {
        for (int i = tid; i < 1024; i += 256) {
            int row = i >> 4, k4 = i & 15;
            S[row * 17 + k4] = *(const float4*)(obs + (size_t)(r0 + row) * 1024 + c * 64 + k4 * 4);
        }
        for (int i = tid; i < 2048; i += 256) {
            int col = i >> 4, k4 = i & 15;
            S[1088 + col * 16 + k4] =
                *(const float4*)(Wq1 + (size_t)(c0 + col) * 2048 + 1024 + c * 64 + k4 * 4);
        }
        __syncthreads();
        const ull2* xr = (const ull2*)(S + (rh * 32 + lane) * 17);
        const ull2* wb = (const ull2*)(S + 1088 + (cgq * 32) * 16);
        for (int k4 = 0; k4 < 16; ++k4) {
            ull2 x = xr[k4];
            #pragma unroll
            for (int j = 0; j < 32; ++j) {
                ull2 w = wb[j * 16 + k4];
                acc[j] = fma2(w.x, x.x, acc[j]);
                acc[j] = fma2(w.y, x.y, acc[j]);
            }
        }
        __syncthreads();
    }
    int r = r0 + rh * 32 + lane;
    #pragma unroll
    for (int j = 0; j < 32; ++j) {
        int col = c0 + cgq * 32 + j;
        g_obsq[(size_t)r * 512 + col] = hsum(acc[j]) + bq1[col];
    }
}

// ======== pre-pass B: g_actemb ========
__global__ void __launch_bounds__(256)
actemb_kernel(const float* __restrict__ act, const float* __restrict__ Wsa,
              const float* __restrict__ bsa) {
    extern __shared__ float4 S[];
    const int tid = threadIdx.x, lane = tid & 31, wrp = tid >> 5;
    const int rt = blockIdx.x >> 3, ct = blockIdx.x & 7;
    const int r0 = rt * 64, c0 = ct * 128;
    const int rh = wrp >> 2, cgq = wrp & 3;

    for (int i = tid; i < 1024; i += 256) {
        int row = i >> 4, k4 = i & 15;
        S[row * 17 + k4] = *(const float4*)(act + (size_t)(r0 + row) * 64 + k4 * 4);
    }
    for (int i = tid; i < 2048; i += 256) {
        int col = i >> 4, k4 = i & 15;
        S[1088 + col * 16 + k4] =
            *(const float4*)(Wsa + (size_t)(c0 + col) * 96 + 32 + k4 * 4);
    }
    __syncthreads();

    u64 acc[32];
    #pragma unroll
    for (int j = 0; j < 32; ++j) acc[j] = 0ull;
    const ull2* xr = (const ull2*)(S + (rh * 32 + lane) * 17);
    const ull2* wb = (const ull2*)(S + 1088 + (cgq * 32) * 16);
    for (int k4 = 0; k4 < 16; ++k4) {
        ull2 x = xr[k4];
        #pragma unroll
        for (int j = 0; j < 32; ++j) {
            ull2 w = wb[j * 16 + k4];
            acc[j] = fma2(w.x, x.x, acc[j]);
            acc[j] = fma2(w.y, x.y, acc[j]);
        }
    }
    int r = r0 + rh * 32 + lane;
    #pragma unroll
    for (int j = 0; j < 32; ++j) {
        int col = c0 + cgq * 32 + j;
        g_actemb[(size_t)r * 1024 + col] = hsum(acc[j]) + bsa[col];
    }
}

// ======== persistent rollout ========
__global__ void __launch_bounds__(NTHR, 1)
rssm_kernel(const float* __restrict__ obs,   const float* __restrict__ act,
            const float* __restrict__ nzp,   const float* __restrict__ nzq,
            const float* __restrict__ Wsa, const float* __restrict__ bsa,
            const float* __restrict__ Wih, const float* __restrict__ bih,
            const float* __restrict__ Whh, const float* __restrict__ bhh,
            const float* __restrict__ Wp1, const float* __restrict__ bp1,
            const float* __restrict__ Wp2, const float* __restrict__ bp2,
            const float* __restrict__ Wq1, const float* __restrict__ bq1,
            const float* __restrict__ Wq2, const float* __restrict__ bq2,
            float* __restrict__ out)
{
    extern __shared__ float4 S[];
    float4* wG = S;                   // 48 gatecols x 257
    float4* xb = S + WG_F4;           // 2048 f4 overlay region

    const int tid  = threadIdx.x;
    const int lane = tid & 31;
    const int wrp  = tid >> 5;
    const int tid2 = tid & 255;
    const int c0g  = blockIdx.x * 8;
    const int r0   = lane & 7;
    const int cq   = lane >> 3;       // 0..3

    // GRU ids: 16 warps = h(4 K-split) x gp(2 oc-groups) x mat(2)
    const int h    = wrp & 3;
    const int gp   = (wrp >> 2) & 1;
    const int mat  = wrp >> 3;        // 0: i-gates (x=emb), 1: h-gates (x=det)
    const int oc   = gp * 4 + cq;     // 0..7
    // ph1/ph3 ids
    const int pr   = (wrp & 7) * 8 + r0;
    const int pc   = (wrp >> 3) * 4 + cq;
    const int h3   = wrp & 7;         // ph3 K-split 8
    const int rw3  = wrp >> 3;        // ph3 row half (= group)

    // ---- init: zero state, load GRU weight slice (once) ----
    for (int i = blockIdx.x * NTHR + tid; i < 64 * 1024; i += NCTA * NTHR)
        g_det[0][i] = 0.f;
    for (int i = blockIdx.x * NTHR + tid; i < 64 * 32; i += NCTA * NTHR)
        g_stoch[i] = 0.f;
    for (int i = tid; i < WG_F4; i += NTHR) {
        int gc = i / 257, k = i - gc * 257;
        if (k < 256) {
            int col = gc / 6, g = gc - col * 6;
            const float* srow = (g < 3)
                ? (Wih + ((size_t)(c0g + col) + 1024 * g) * 1024)
                : (Whh + ((size_t)(c0g + col) + 1024 * (g - 3)) * 1024);
            wG[i] = *(const float4*)(srow + k * 4);
        }
    }
    gbar();

    // GRU per-thread weight bases (gc = oc*6 + mat*3 + m)
    const float4* wgm0 = wG + (oc * 6 + mat * 3 + 0) * 257;
    const float4* wgm1 = wG + (oc * 6 + mat * 3 + 1) * 257;
    const float4* wgm2 = wG + (oc * 6 + mat * 3 + 2) * 257;
    const int k4a = h * 2, k4b = h * 2 + 1;
    const int xoa = r0 * 8 + (k4a ^ r0);
    const int xob = r0 * 8 + (k4b ^ r0);

    // GRU group staging (each group stages its own 512-f4 half)
    const int pi0 = tid2 * 2, pi1 = pi0 + 1;
    const int prw0 = pi0 >> 3, pk0 = pi0 & 7;
    const int prw1 = pi1 >> 3, pk1 = pi1 & 7;
    const int pd0 = prw0 * 8 + (pk0 ^ (prw0 & 7));
    const int pd1 = prw1 * 8 + (pk1 ^ (prw1 & 7));

    for (int t = 0; t < 256; ++t) {
        const int p = t & 1;
        const float* detP = g_det[p];
        float*       detN = g_det[p ^ 1];

        // ===== phase 1: emb = relu(stoch @ Ws^T + actemb), K=32 =====
        {
            float4* stS = xb;           // 64 x 9
            float4* wS1 = xb + 576;     // 8 x 9
            {
                int row = tid >> 3, k4 = tid & 7;
                stS[row * 9 + k4] = *(const float4*)(g_stoch + row * 32 + k4 * 4);
            }
            if (tid < 64) {
                int c = tid >> 3, k4 = tid & 7;
                wS1[c * 9 + k4] = *(const float4*)(Wsa + (size_t)(c0g + c) * 96 + k4 * 4);
            }
            __syncthreads();
            u64 a = 0;
            #pragma unroll
            for (int k4 = 0; k4 < 8; ++k4) {
                ull2 x = *(const ull2*)(stS + pr * 9 + k4);
                ull2 w = *(const ull2*)(wS1 + pc * 9 + k4);
                a = fma2(w.x, x.x, a); a = fma2(w.y, x.y, a);
            }
            int col = c0g + pc;
            float base = g_actemb[((size_t)pr * 256 + t) * 1024 + col];
            g_emb[(size_t)pr * 1024 + col] = fmaxf(hsum(a) + base, 0.f);
        }
        gbar();

        // ===== phase 2: GRU (split sync domains: mat0 | mat1) =====
        {
            float4* gxb = xb + mat * 1024;     // group double buffer (2 x 512)
            const int bid = mat + 1;           // named barrier id
            const float* psrc = mat ? detP : g_emb;
            const float* ps0 = psrc + prw0 * 1024 + pk0 * 4;
            const float* ps1 = psrc + prw1 * 1024 + pk1 * 4;

            u64 acc[24];
            #pragma unroll
            for (int n = 0; n < 24; ++n) acc[n] = 0ull;

            gxb[pd0] = *(const float4*)(ps0);
            gxb[pd1] = *(const float4*)(ps1);
            barg(bid);

            for (int j = 0; j < 32; ++j) {
                float4 pf0, pf1;
                if (j < 31) {
                    pf0 = *(const float4*)(ps0 + (j + 1) * 32);
                    pf1 = *(const float4*)(ps1 + (j + 1) * 32);
                }
                const float4* xm = gxb + (j & 1) * 512;
                ull2 wa0 = *(const ull2*)(wgm0 + j * 8 + k4a);
                ull2 wb0 = *(const ull2*)(wgm1 + j * 8 + k4a);
                ull2 wc0 = *(const ull2*)(wgm2 + j * 8 + k4a);
                ull2 wa1 = *(const ull2*)(wgm0 + j * 8 + k4b);
                ull2 wb1 = *(const ull2*)(wgm1 + j * 8 + k4b);
                ull2 wc1 = *(const ull2*)(wgm2 + j * 8 + k4b);
                #pragma unroll
                for (int i = 0; i < 8; ++i) {
                    ull2 x = *(const ull2*)(xm + xoa + 64 * i);
                    acc[i*3+0] = fma2(wa0.x, x.x, acc[i*3+0]);
                    acc[i*3+0] = fma2(wa0.y, x.y, acc[i*3+0]);
                    acc[i*3+1] = fma2(wb0.x, x.x, acc[i*3+1]);
                    acc[i*3+1] = fma2(wb0.y, x.y, acc[i*3+1]);
                    acc[i*3+2] = fma2(wc0.x, x.x, acc[i*3+2]);
                    acc[i*3+2] = fma2(wc0.y, x.y, acc[i*3+2]);
                }
                #pragma unroll
                for (int i = 0; i < 8; ++i) {
                    ull2 x = *(const ull2*)(xm + xob + 64 * i);
                    acc[i*3+0] = fma2(wa1.x, x.x, acc[i*3+0]);
                    acc[i*3+0] = fma2(wa1.y, x.y, acc[i*3+0]);
                    acc[i*3+1] = fma2(wb1.x, x.x, acc[i*3+1]);
                    acc[i*3+1] = fma2(wb1.y, x.y, acc[i*3+1]);
                    acc[i*3+2] = fma2(wc1.x, x.x, acc[i*3+2]);
                    acc[i*3+2] = fma2(wc1.y, x.y, acc[i*3+2]);
                }
                if (j < 31) {
                    float4* nb = gxb + ((j + 1) & 1) * 512;
                    nb[pd0] = pf0;
                    nb[pd1] = pf1;
                }
                barg(bid);
            }
            __syncthreads();    // join both groups before smem overlay reuse

            float f[24];
            #pragma unroll
            for (int n = 0; n < 24; ++n) f[n] = hsum(acc[n]);
            float* R = (float*)xb;

            if (h >= 2) {
                float* pp = R + (((h - 2) * 4 + gp * 2 + mat) * 32 + lane) * 24;
                #pragma unroll
                for (int n = 0; n < 24; ++n) pp[n] = f[n];
            }
            __syncthreads();
            if (h < 2) {
                const float* pp = R + ((h * 4 + gp * 2 + mat) * 32 + lane) * 24;
                #pragma unroll
                for (int n = 0; n < 24; ++n) f[n] += pp[n];
            }
            __syncthreads();
            if (h == 1) {
                float* pp = R + ((gp * 2 + mat) * 32 + lane) * 24;
                #pragma unroll
                for (int n = 0; n < 24; ++n) pp[n] = f[n];
            }
            __syncthreads();
            if (h == 0) {
                const float* pp = R + ((gp * 2 + mat) * 32 + lane) * 24;
                #pragma unroll
                for (int n = 0; n < 24; ++n) f[n] += pp[n];
            }
            __syncthreads();
            if (h == 0 && mat == 1) {
                int col = c0g + oc;
                float* pp = R + (gp * 32 + lane) * 24;
                #pragma unroll
                for (int i = 0; i < 8; ++i)
                    #pragma unroll
                    for (int m = 0; m < 3; ++m)
                        pp[i * 3 + m] = f[i * 3 + m] + bhh[col + 1024 * m];
            }
            __syncthreads();
            if (h == 0 && mat == 0) {
                int col = c0g + oc;
                const float* ph = R + (gp * 32 + lane) * 24;
                #pragma unroll
                for (int i = 0; i < 8; ++i) {
                    int row = r0 + 8 * i;
                    float ir = f[i*3+0] + bih[col];
                    float iz = f[i*3+1] + bih[col + 1024];
                    float in = f[i*3+2] + bih[col + 2048];
                    float hr = ph[i*3+0], hz = ph[i*3+1], hn = ph[i*3+2];
                    float r  = sigm(ir + hr);
                    float z  = sigm(iz + hz);
                    float n  = tanhf(in + r * hn);
                    float hp = detP[(size_t)row * 1024 + col];
                    float hw = (1.f - z) * n + z * hp;
                    detN[(size_t)row * 1024 + col] = hw;
                    out[((size_t)row * 256 + t) * 1216 + col] = hw;
                }
            }
        }
        gbar();

        // ===== phase 3: h1 / hq first layers (split domains: row halves) =====
        {
            const bool isQ = blockIdx.x & 1;
            const int  c0  = (blockIdx.x >> 1) * 8;
            const float* W1 = isQ ? Wq1 : Wp1;
            const size_t K1 = isQ ? 2048 : 1024;
            const int g   = rw3;               // group = row half
            const int bid = g + 3;             // named barrier ids 3,4
            float4* gxb = xb + g * 672;        // per-group double buffer (2 x 336)

            // staging: x slot (1 f4) for all 256, w slot for tid2<64
            const int xrow = tid2 >> 3, xk4 = tid2 & 7;      // local row 0..31
            const float* xsrc = detN + (size_t)(g * 32 + xrow) * 1024 + xk4 * 4;
            const int xdst = xrow * 8 + (xk4 ^ (xrow & 7));
            const float* wsrc = W1;
            int wdst = 0;
            if (tid2 < 64) {
                int wc = tid2 >> 3, wk = tid2 & 7;
                wsrc = W1 + (size_t)(c0 + wc) * K1 + wk * 4;
                wdst = 256 + wc * 9 + wk;
            }

            u64 acc[8];
            #pragma unroll
            for (int n = 0; n < 8; ++n) acc[n] = 0ull;

            gxb[xdst] = *(const float4*)(xsrc);
            if (tid2 < 64) gxb[wdst] = *(const float4*)(wsrc);
            barg(bid);

            const int xbase = r0 * 8 + (h3 ^ r0);
            for (int j = 0; j < 32; ++j) {
                float4 pfx, pfw;
                if (j < 31) {
                    pfx = *(const float4*)(xsrc + (j + 1) * 32);
                    if (tid2 < 64) pfw = *(const float4*)(wsrc + (j + 1) * 32);
                }
                const float4* buf = gxb + (j & 1) * 336;
                ull2 w0 = *(const ull2*)(buf + 256 + (cq * 2) * 9 + h3);
                ull2 w1 = *(const ull2*)(buf + 256 + (cq * 2 + 1) * 9 + h3);
                #pragma unroll
                for (int i = 0; i < 4; ++i) {
                    ull2 x = *(const ull2*)(buf + xbase + 64 * i);
                    acc[i*2+0] = fma2(w0.x, x.x, acc[i*2+0]);
                    acc[i*2+0] = fma2(w0.y, x.y, acc[i*2+0]);
                    acc[i*2+1] = fma2(w1.x, x.x, acc[i*2+1]);
                    acc[i*2+1] = fma2(w1.y, x.y, acc[i*2+1]);
                }
                if (j < 31) {
                    float4* nb = gxb + ((j + 1) & 1) * 336;
                    nb[xdst] = pfx;
                    if (tid2 < 64) nb[wdst] = pfw;
                }
                barg(bid);
            }
            __syncthreads();    // join groups before overlay reuse

            float f[8];
            #pragma unroll
            for (int n = 0; n < 8; ++n) f[n] = hsum(acc[n]);
            float* Rf = (float*)xb;
            if (h3 > 0) {
                float* pp = Rf + (((h3 - 1) * 2 + rw3) * 32 + lane) * 8;
                #pragma unroll
                for (int n = 0; n < 8; ++n) pp[n] = f[n];
            }
            __syncthreads();
            if (h3 == 0) {
                for (int s = 0; s < 7; ++s) {
                    const float* pp = Rf + ((s * 2 + rw3) * 32 + lane) * 8;
                    #pragma unroll
                    for (int n = 0; n < 8; ++n) f[n] += pp[n];
                }
                float* dst = isQ ? g_hq : g_h1;
                #pragma unroll
                for (int i = 0; i < 4; ++i) {
                    int row = rw3 * 32 + r0 + 8 * i;
                    #pragma unroll
                    for (int c = 0; c < 2; ++c) {
                        int col = c0 + cq * 2 + c;
                        float base = isQ ? g_obsq[((size_t)row * 256 + t) * 512 + col]
                                         : bp1[col];
                        dst[(size_t)row * 512 + col] = fmaxf(f[i*2+c] + base, 0.f);
                    }
                }
            }
        }
        gbar();

        // ===== phase 4: heads =====
        {
            const int gw = blockIdx.x * 16 + wrp;
            #pragma unroll
            for (int i = 0; i < 2; ++i) {
                int pi    = gw * 2 + i;
                int which = pi & 1;
                int s     = (pi >> 1) & 31;
                int bb    = pi >> 6;
                const float* hv = (which ? g_hq : g_h1) + (size_t)bb * 512;
                const float* W2 = which ? Wq2 : Wp2;
                u64 am = 0, asd = 0;
                #pragma unroll
                for (int q = 0; q < 4; ++q) {
                    float4 xf = __ldcg((const float4*)(hv + lane * 16 + q * 4));
                    ull2 x = *(ull2*)&xf;
                    ull2 u = *(const ull2*)(W2 + (size_t)s * 512 + lane * 16 + q * 4);
                    ull2 v = *(const ull2*)(W2 + (size_t)(s + 32) * 512 + lane * 16 + q * 4);
                    am  = fma2(u.x, x.x, am);  am  = fma2(u.y, x.y, am);
                    asd = fma2(v.x, x.x, asd); asd = fma2(v.y, x.y, asd);
                }
                float sm = hsum(am), ss = hsum(asd);
                #pragma unroll
                for (int o = 16; o; o >>= 1) {
                    sm += __shfl_xor_sync(0xffffffffu, sm, o);
                    ss += __shfl_xor_sync(0xffffffffu, ss, o);
                }
                if (lane == 0) {
                    const float* b2 = which ? bq2 : bp2;
                    float mean = sm + b2[s];
                    float stdv = softplusf(ss + b2[s + 32]) + 1e-5f;
                    const float* nz = which ? nzq : nzp;
                    float e  = nz[((size_t)bb * 256 + t) * 32 + s];
                    float st = mean + stdv * e;
                    size_t base = ((size_t)bb * 256 + t) * 1216 + 1024 + which * 96;
                    out[base + s]      = mean;
                    out[base + 32 + s] = stdv;
                    out[base + 64 + s] = st;
                    if (which) g_stoch[bb * 32 + s] = st;
                }
            }
        }
        gbar();
    }
}

extern "C" void kernel_launch(void* const* d_in, const int* in_sizes, int n_in,
                              void* d_out, int out_size) {
    (void)in_sizes; (void)n_in; (void)out_size;
    cudaFuncSetAttribute((const void*)obsq_kernel,
                         cudaFuncAttributeMaxDynamicSharedMemorySize, 50176);
    cudaFuncSetAttribute((const void*)actemb_kernel,
                         cudaFuncAttributeMaxDynamicSharedMemorySize, 50176);
    cudaFuncSetAttribute((const void*)rssm_kernel,
                         cudaFuncAttributeMaxDynamicSharedMemorySize, SMEM_BYTES);
    actemb_kernel<<<2048, 256, 50176>>>(
        (const float*)d_in[1], (const float*)d_in[4], (const float*)d_in[5]);
    obsq_kernel<<<1024, 256, 50176>>>(
        (const float*)d_in[0], (const float*)d_in[14], (const float*)d_in[15]);
    rssm_kernel<<<NCTA, NTHR, SMEM_BYTES>>>(
        (const float*)d_in[0],  (const float*)d_in[1],
        (const float*)d_in[2],  (const float*)d_in[3],
        (const float*)d_in[4],  (const float*)d_in[5],
        (const float*)d_in[6],  (const float*)d_in[7],
        (const float*)d_in[8],  (const float*)d_in[9],
        (const float*)d_in[10], (const float*)d_in[11],
        (const float*)d_in[12], (const float*)d_in[13],
        (const float*)d_in[14], (const float*)d_in[15],
        (const float*)d_in[16], (const float*)d_in[17],
        (float*)d_out);
}